// round 1
// baseline (speedup 1.0000x reference)
#include <cuda_runtime.h>

#define DD 48
#define HH 256
#define WW 256
#define HM 128
#define WM 128
#define PHN 4

// ---------------------------------------------------------------------------
// Channel-0 passthrough: copy image (1,1,48,256,256,2) fp32 -> out[0:6291456]
// ---------------------------------------------------------------------------
__global__ __launch_bounds__(256) void copy_img_kernel(
    const float4* __restrict__ in, float4* __restrict__ out, int n4)
{
    int i = blockIdx.x * blockDim.x + threadIdx.x;
    if (i < n4) out[i] = in[i];
}

// ---------------------------------------------------------------------------
// Fused: mvf trilinear upsample (H/W x2, exact 0.25/0.75 weights, edge-clamped)
//        -> scale (1,2,2) -> add identity grid -> trilinear grid-sample of the
//        2-channel image (zeros padding, align_corners=True) -> write channel 1+p
// One thread per output voxel (p, z, y, x). Block covers one full W row.
// ---------------------------------------------------------------------------
__global__ __launch_bounds__(256) void mvf_warp_kernel(
    const float* __restrict__ image,   // [DD][HH][WW][2]
    const float* __restrict__ mvf,     // [PHN][3][DD][HM][WM]
    float* __restrict__ out)           // [5][DD][HH][WW][2]; channels 1..4 written here
{
    const int x = threadIdx.x;      // 0..255
    const int y = blockIdx.x;       // 0..255
    const int z = blockIdx.y;       // 0..47
    const int p = blockIdx.z;       // 0..3

    // ---- MVF upsample source coords (jax.image.resize, linear, 128->256) ----
    // sample_f = (o+0.5)*0.5 - 0.5 = o*0.5 - 0.25 ; boundary renorm == clamp.
    float fy = fminf(fmaxf(y * 0.5f - 0.25f, 0.0f), (float)(HM - 1));
    float fx = fminf(fmaxf(x * 0.5f - 0.25f, 0.0f), (float)(WM - 1));
    int   y0 = (int)fy;
    int   x0 = (int)fx;
    float wy = fy - (float)y0;
    float wx = fx - (float)x0;
    int   y1 = min(y0 + 1, HM - 1);
    int   x1 = min(x0 + 1, WM - 1);

    const int mbase = ((p * 3) * DD + z) * (HM * WM);
    const int cstr  = DD * HM * WM;

    float m[3];
    #pragma unroll
    for (int c = 0; c < 3; ++c) {
        const float* mp = mvf + mbase + c * cstr;
        float v00 = __ldg(mp + y0 * WM + x0);
        float v01 = __ldg(mp + y0 * WM + x1);
        float v10 = __ldg(mp + y1 * WM + x0);
        float v11 = __ldg(mp + y1 * WM + x1);
        float r0 = (1.0f - wx) * v00 + wx * v01;
        float r1 = (1.0f - wx) * v10 + wx * v11;
        m[c] = (1.0f - wy) * r0 + wy * r1;
    }

    // ---- absolute sample coordinates (z,y,x), flow scaled by (1,2,2) ----
    float cz = (float)z + m[0];
    float cy = (float)y + 2.0f * m[1];
    float cx = (float)x + 2.0f * m[2];

    float zf = floorf(cz), yf = floorf(cy), xf = floorf(cx);
    int   zi = (int)zf,    yi = (int)yf,    xi = (int)xf;
    float wz  = cz - zf;
    float wyy = cy - yf;
    float wxx = cx - xf;

    const float2* img2 = (const float2*)image;

    float acc0 = 0.0f, acc1 = 0.0f;
    #pragma unroll
    for (int dz = 0; dz < 2; ++dz) {
        int zz = zi + dz;
        float wzv = dz ? wz : (1.0f - wz);
        int zc = min(max(zz, 0), DD - 1);
        bool zok = ((unsigned)zz < (unsigned)DD);
        #pragma unroll
        for (int dy = 0; dy < 2; ++dy) {
            int yy = yi + dy;
            float wyv = dy ? wyy : (1.0f - wyy);
            int yc = min(max(yy, 0), HH - 1);
            bool yok = ((unsigned)yy < (unsigned)HH);
            int rowbase = (zc * HH + yc) * WW;
            #pragma unroll
            for (int dx = 0; dx < 2; ++dx) {
                int xx = xi + dx;
                float wxv = dx ? wxx : (1.0f - wxx);
                int xc = min(max(xx, 0), WW - 1);
                bool ok = zok && yok && ((unsigned)xx < (unsigned)WW);
                float w = ok ? (wzv * wyv * wxv) : 0.0f;
                float2 v = __ldg(img2 + (rowbase + xc));
                acc0 += w * v.x;
                acc1 += w * v.y;
            }
        }
    }

    float2* o = (float2*)out + (((1 + p) * DD + z) * HH + y) * WW + x;
    *o = make_float2(acc0, acc1);
}

extern "C" void kernel_launch(void* const* d_in, const int* in_sizes, int n_in,
                              void* d_out, int out_size)
{
    const float* image = (const float*)d_in[0];   // 6291456 floats
    const float* mvf   = (const float*)d_in[1];   // 9437184 floats
    float* out = (float*)d_out;                   // 31457280 floats

    // channel 0: straight copy of the input image
    const int n4 = (DD * HH * WW * 2) / 4;        // 1572864 float4
    copy_img_kernel<<<(n4 + 255) / 256, 256>>>((const float4*)image, (float4*)out, n4);

    // channels 1..4: fused upsample + warp
    dim3 grid(HH, DD, PHN);
    mvf_warp_kernel<<<grid, 256>>>(image, mvf, out);
}